// round 1
// baseline (speedup 1.0000x reference)
#include <cuda_runtime.h>
#include <stdint.h>

// Problem constants (from reference: B=64, C=256, H=64, W=64, k=8)
#define BB   64
#define CC   256
#define HH   64
#define WW   64
#define HW   (HH * WW)          // 4096
#define NPB  (CC * HW)          // 1<<20 elements per batch
#define KK   8
#define OUTC (CC + 3)           // 259

#define CHUNKS 32               // chunks per batch (pass-1 blocks per batch)
#define CHUNK  (NPB / CHUNKS)   // 32768 elements per chunk
#define TPB    256

// scratch: per (batch, chunk) top-8 keys
__device__ unsigned long long g_scratch[BB * CHUNKS * KK];

// monotonic float->uint mapping (total order matches float compare)
__device__ __forceinline__ uint32_t f2mono(float f) {
    uint32_t b = __float_as_uint(f);
    return b ^ ((uint32_t)((int32_t)b >> 31) | 0x80000000u);
}
__device__ __forceinline__ float mono2f(uint32_t m) {
    uint32_t b = (m & 0x80000000u) ? (m ^ 0x80000000u) : ~m;
    return __uint_as_float(b);
}

__device__ __forceinline__ unsigned long long make_key(float v, uint32_t idx) {
    return ((unsigned long long)f2mono(v) << 32) | (uint32_t)(~idx);
}

__device__ __forceinline__ void consider(unsigned long long (&top)[KK],
                                         float v, uint32_t idx) {
    unsigned long long key = make_key(v, idx);
    if (key > top[KK - 1]) {
        top[KK - 1] = key;
        #pragma unroll
        for (int j = KK - 1; j > 0; --j) {
            if (top[j] > top[j - 1]) {
                unsigned long long t = top[j];
                top[j] = top[j - 1];
                top[j - 1] = t;
            }
        }
    }
}

// Pass 1: each block scans one 32K chunk of one batch, emits its top-8 keys.
__global__ __launch_bounds__(TPB)
void topk_pass1(const float* __restrict__ x) {
    const int b = blockIdx.x;
    const int chunk = blockIdx.y;
    const int tid = threadIdx.x;

    const float4* p = (const float4*)(x + (size_t)b * NPB + (size_t)chunk * CHUNK);
    const uint32_t ibase = (uint32_t)chunk * CHUNK;

    unsigned long long top[KK];
    #pragma unroll
    for (int j = 0; j < KK; ++j) top[j] = 0ull;

    // CHUNK/(TPB*4) = 32 iterations; coalesced float4 streaming
    #pragma unroll 4
    for (int it = 0; it < CHUNK / (TPB * 4); ++it) {
        int e = it * TPB + tid;               // float4 index within chunk
        float4 v = p[e];
        uint32_t idx = ibase + (uint32_t)e * 4u;
        consider(top, v.x, idx + 0u);
        consider(top, v.y, idx + 1u);
        consider(top, v.z, idx + 2u);
        consider(top, v.w, idx + 3u);
    }

    // Block-level top-8 of 256*8 = 2048 candidates
    __shared__ unsigned long long cand[TPB * KK];
    __shared__ unsigned long long wmax[TPB / 32];
    __shared__ unsigned long long winner;

    #pragma unroll
    for (int j = 0; j < KK; ++j) cand[tid * KK + j] = top[j];
    __syncthreads();

    const int lane = tid & 31;
    const int warp = tid >> 5;

    unsigned long long* outp = &g_scratch[((size_t)b * CHUNKS + chunk) * KK];

    for (int sel = 0; sel < KK; ++sel) {
        unsigned long long m = 0ull;
        #pragma unroll
        for (int j = 0; j < KK; ++j) {
            unsigned long long c = cand[tid * KK + j];
            if (c > m) m = c;
        }
        #pragma unroll
        for (int off = 16; off > 0; off >>= 1) {
            unsigned long long o = __shfl_down_sync(0xFFFFFFFFu, m, off);
            if (o > m) m = o;
        }
        if (lane == 0) wmax[warp] = m;
        __syncthreads();
        if (tid == 0) {
            unsigned long long w = 0ull;
            #pragma unroll
            for (int q = 0; q < TPB / 32; ++q)
                if (wmax[q] > w) w = wmax[q];
            winner = w;
            outp[sel] = w;
        }
        __syncthreads();
        unsigned long long w = winner;
        // keys are unique (unique indices) -> clear exactly the winning slot
        #pragma unroll
        for (int j = 0; j < KK; ++j)
            if (cand[tid * KK + j] == w) cand[tid * KK + j] = 0ull;
        __syncthreads();
    }
}

// Pass 2: one block per batch. Reduce 32*8=256 candidate keys to sorted top-8,
// then write the [8, 259] output row.
__global__ __launch_bounds__(TPB)
void topk_pass2(float* __restrict__ out) {
    const int b = blockIdx.x;
    const int tid = threadIdx.x;
    const int lane = tid & 31;
    const int warp = tid >> 5;

    unsigned long long key = g_scratch[(size_t)b * (CHUNKS * KK) + tid];

    __shared__ unsigned long long wmax[TPB / 32];
    __shared__ unsigned long long winner;
    __shared__ unsigned long long topk[KK];

    for (int sel = 0; sel < KK; ++sel) {
        unsigned long long m = key;
        #pragma unroll
        for (int off = 16; off > 0; off >>= 1) {
            unsigned long long o = __shfl_down_sync(0xFFFFFFFFu, m, off);
            if (o > m) m = o;
        }
        if (lane == 0) wmax[warp] = m;
        __syncthreads();
        if (tid == 0) {
            unsigned long long w = 0ull;
            #pragma unroll
            for (int q = 0; q < TPB / 32; ++q)
                if (wmax[q] > w) w = wmax[q];
            winner = w;
            topk[sel] = w;
        }
        __syncthreads();
        if (key == winner) key = 0ull;   // unique keys: removes exactly one
        __syncthreads();
    }

    float* ob = out + (size_t)b * KK * OUTC;

    // zero the 8*259 floats for this batch
    for (int i = tid; i < KK * OUTC; i += TPB) ob[i] = 0.0f;
    __syncthreads();

    if (tid < KK) {
        unsigned long long k = topk[tid];
        float val = mono2f((uint32_t)(k >> 32));
        uint32_t idx = ~((uint32_t)k);          // index within batch (c*HW + y*W + x)
        int c   = (int)(idx >> 12);             // / 4096
        int rem = (int)(idx & 4095u);
        int y   = rem >> 6;                     // / 64
        int xq  = rem & 63;
        float* row = ob + tid * OUTC;
        row[c]        = 1.0f;
        row[CC + 0]   = val;
        row[CC + 1]   = (float)xq * (1.0f / (WW - 1));
        row[CC + 2]   = (float)y  * (1.0f / (HH - 1));
    }
}

extern "C" void kernel_launch(void* const* d_in, const int* in_sizes, int n_in,
                              void* d_out, int out_size) {
    const float* x = (const float*)d_in[0];
    float* out = (float*)d_out;

    dim3 g1(BB, CHUNKS);
    topk_pass1<<<g1, TPB>>>(x);
    topk_pass2<<<BB, TPB>>>(out);
}

// round 3
// speedup vs baseline: 2.8348x; 2.8348x over previous
#include <cuda_runtime.h>
#include <stdint.h>

// Problem: B=64, C=256, H=64, W=64, k=8.  out: [64, 8, 259] fp32
#define BB   64
#define CC   256
#define HH   64
#define WW   64
#define NPB  (1 << 20)          // elements per batch (C*H*W)
#define KK   8
#define OUTC (CC + 3)           // 259
#define CAP  4096               // candidate capacity per batch

#define CH     8                // filter chunks per batch
#define CHUNK  (NPB / CH)       // 131072 elements
#define TPB    256
#define GROUPS 16               // groups/thread in filter (16*32 = 512 elem/thread)

typedef unsigned long long u64;
typedef unsigned int u32;

__device__ u64   g_cand[BB * CAP];
__device__ int   g_count[BB];
__device__ float g_tf[BB];      // float threshold (exact compare in slow path)
__device__ u32   g_tb[BB];      // bit threshold for fast unsigned compare (0 if T<0)

// monotonic float<->uint mapping (total order matches float compare)
__device__ __forceinline__ u32 f2mono(float f) {
    u32 b = __float_as_uint(f);
    return b ^ ((u32)((int)b >> 31) | 0x80000000u);
}
__device__ __forceinline__ float mono2f(u32 m) {
    u32 b = (m & 0x80000000u) ? (m ^ 0x80000000u) : ~m;
    return __uint_as_float(b);
}
__device__ __forceinline__ u64 make_key(float v, u32 idx) {
    return ((u64)f2mono(v) << 32) | (u32)(~idx);
}

// exact top-8 insert by key (value desc, index asc) — matches lax.top_k
__device__ __forceinline__ void consider_key(u64 (&top)[KK], u64 key) {
    if (key > top[KK - 1]) {
        top[KK - 1] = key;
        #pragma unroll
        for (int j = KK - 1; j > 0; --j) {
            if (top[j] > top[j - 1]) { u64 t = top[j]; top[j] = top[j - 1]; top[j - 1] = t; }
        }
    }
}

// value-only top-8 insert (threshold estimation)
__device__ __forceinline__ void considerf(float (&t)[KK], float v) {
    if (v > t[KK - 1]) {
        t[KK - 1] = v;
        #pragma unroll
        for (int j = KK - 1; j > 0; --j) {
            if (t[j] > t[j - 1]) { float s = t[j]; t[j] = t[j - 1]; t[j - 1] = s; }
        }
    }
}

// ───────────────────────── Pass A: sample → per-batch threshold ─────────────
// Samples first 65536 elements of each batch. 8th-largest-of-a-subset <= true
// 8th-largest, so filtering with v >= T never drops a true top-8 element.
__global__ __launch_bounds__(TPB)
void k_thresh(const float* __restrict__ x) {
    const int b = blockIdx.x;
    const int tid = threadIdx.x;
    if (tid == 0) g_count[b] = 0;

    const float4* __restrict__ p = (const float4*)(x + (size_t)b * NPB);
    float t[KK];
    #pragma unroll
    for (int j = 0; j < KK; ++j) t[j] = -__int_as_float(0x7f800000);  // -inf

    #pragma unroll 4
    for (int i = 0; i < 64; ++i) {
        float4 v = p[i * TPB + tid];
        considerf(t, v.x); considerf(t, v.y); considerf(t, v.z); considerf(t, v.w);
    }

    __shared__ float cf[TPB * KK];
    __shared__ float wmaxf[TPB / 32];
    __shared__ float winf;
    #pragma unroll
    for (int j = 0; j < KK; ++j) cf[tid * KK + j] = t[j];
    __syncthreads();

    const int lane = tid & 31, warp = tid >> 5;
    for (int sel = 0; sel < KK; ++sel) {
        float m = -__int_as_float(0x7f800000);
        #pragma unroll
        for (int j = 0; j < KK; ++j) { float c = cf[tid * KK + j]; if (c > m) m = c; }
        #pragma unroll
        for (int off = 16; off > 0; off >>= 1) {
            float o = __shfl_down_sync(0xFFFFFFFFu, m, off);
            if (o > m) m = o;
        }
        if (lane == 0) wmaxf[warp] = m;
        __syncthreads();
        if (tid == 0) {
            float w = -__int_as_float(0x7f800000);
            #pragma unroll
            for (int q = 0; q < TPB / 32; ++q) if (wmaxf[q] > w) w = wmaxf[q];
            winf = w;
        }
        __syncthreads();
        float w = winf;
        #pragma unroll
        for (int j = 0; j < KK; ++j)
            if (cf[tid * KK + j] == w) cf[tid * KK + j] = -__int_as_float(0x7f800000);
        __syncthreads();
    }
    if (tid == 0) {
        float T = winf;
        g_tf[b] = T;
        g_tb[b] = (T >= 0.0f) ? __float_as_uint(T) : 0u;  // T<0 -> everything slow path
    }
}

// ───────────────────────── Pass B: stream + filter + compact ────────────────
__device__ __forceinline__ void emit(int b, float v, u32 idx) {
    int s = atomicAdd(&g_count[b], 1);
    if (s < CAP) g_cand[b * CAP + s] = make_key(v, idx);
}

__global__ __launch_bounds__(TPB)
void k_filter(const float* __restrict__ x) {
    const int c = blockIdx.x;
    const int b = blockIdx.y;
    const int tid = threadIdx.x;
    const u32 TB = g_tb[b];
    const float TF = g_tf[b];
    const u32 cbase = (u32)c * CHUNK;
    const uint4* __restrict__ p = (const uint4*)(x + (size_t)b * NPB + cbase);

    #pragma unroll 4
    for (int i = 0; i < GROUPS; ++i) {
        uint4 q[8];
        #pragma unroll
        for (int j = 0; j < 8; ++j)
            q[j] = p[(i * 8 + j) * TPB + tid];

        // DPX 3-input unsigned max tree: 32 values -> 1 in 16 ops.
        // Unsigned bit compare is exact for non-negative floats; negatives/NaN
        // compare high -> false positives only (rechecked exactly below).
        u32 s0 = __vimax3_u32(q[0].x, q[0].y, q[0].z);
        u32 s1 = __vimax3_u32(q[1].x, q[1].y, q[1].z);
        u32 s2 = __vimax3_u32(q[2].x, q[2].y, q[2].z);
        u32 s3 = __vimax3_u32(q[3].x, q[3].y, q[3].z);
        u32 s4 = __vimax3_u32(q[4].x, q[4].y, q[4].z);
        u32 s5 = __vimax3_u32(q[5].x, q[5].y, q[5].z);
        u32 s6 = __vimax3_u32(q[6].x, q[6].y, q[6].z);
        u32 s7 = __vimax3_u32(q[7].x, q[7].y, q[7].z);
        u32 u0 = __vimax3_u32(s0, s1, q[0].w);
        u32 u1 = __vimax3_u32(s2, s3, q[1].w);
        u32 u2 = __vimax3_u32(s4, s5, q[2].w);
        u32 u3 = __vimax3_u32(s6, s7, q[3].w);
        u32 v0 = __vimax3_u32(u0, u1, q[4].w);
        u32 v1 = __vimax3_u32(u2, u3, q[5].w);
        u32 mm = __vimax3_u32(v0, v1, q[6].w);
        mm     = __vimax3_u32(mm, q[7].w, 0u);

        if (mm >= TB) {
            #pragma unroll
            for (int j = 0; j < 8; ++j) {
                u32 e = cbase + ((u32)(i * 8 + j) * TPB + (u32)tid) * 4u;
                float v0f = __uint_as_float(q[j].x);
                float v1f = __uint_as_float(q[j].y);
                float v2f = __uint_as_float(q[j].z);
                float v3f = __uint_as_float(q[j].w);
                if (v0f >= TF) emit(b, v0f, e + 0u);
                if (v1f >= TF) emit(b, v1f, e + 1u);
                if (v2f >= TF) emit(b, v2f, e + 2u);
                if (v3f >= TF) emit(b, v3f, e + 3u);
            }
        }
    }
}

// ───────────────────────── Pass C: select exact top-8 + emit output ────────
__global__ __launch_bounds__(TPB)
void k_select(const float* __restrict__ x, float* __restrict__ out) {
    const int b = blockIdx.x;
    const int tid = threadIdx.x;
    const int cnt = g_count[b];

    u64 top[KK];
    #pragma unroll
    for (int j = 0; j < KK; ++j) top[j] = 0ull;

    if (cnt >= KK && cnt <= CAP) {
        for (int i = tid; i < cnt; i += TPB)
            consider_key(top, g_cand[b * CAP + i]);
    } else {
        // fallback: exact brute-force scan of the whole batch (cold path)
        const float4* __restrict__ p = (const float4*)(x + (size_t)b * NPB);
        for (int i = tid; i < NPB / 4; i += TPB) {
            float4 v = p[i];
            u32 e = (u32)i * 4u;
            consider_key(top, make_key(v.x, e + 0u));
            consider_key(top, make_key(v.y, e + 1u));
            consider_key(top, make_key(v.z, e + 2u));
            consider_key(top, make_key(v.w, e + 3u));
        }
    }

    __shared__ u64 cand[TPB * KK];
    __shared__ u64 wmax[TPB / 32];
    __shared__ u64 winner;
    __shared__ u64 topk[KK];
    #pragma unroll
    for (int j = 0; j < KK; ++j) cand[tid * KK + j] = top[j];
    __syncthreads();

    const int lane = tid & 31, warp = tid >> 5;
    for (int sel = 0; sel < KK; ++sel) {
        u64 m = 0ull;
        #pragma unroll
        for (int j = 0; j < KK; ++j) { u64 cc = cand[tid * KK + j]; if (cc > m) m = cc; }
        #pragma unroll
        for (int off = 16; off > 0; off >>= 1) {
            u64 o = __shfl_down_sync(0xFFFFFFFFu, m, off);
            if (o > m) m = o;
        }
        if (lane == 0) wmax[warp] = m;
        __syncthreads();
        if (tid == 0) {
            u64 w = 0ull;
            #pragma unroll
            for (int q = 0; q < TPB / 32; ++q) if (wmax[q] > w) w = wmax[q];
            winner = w;
            topk[sel] = w;
        }
        __syncthreads();
        u64 w = winner;
        #pragma unroll
        for (int j = 0; j < KK; ++j)
            if (cand[tid * KK + j] == w) cand[tid * KK + j] = 0ull;
        __syncthreads();
    }

    float* ob = out + (size_t)b * KK * OUTC;
    for (int i = tid; i < KK * OUTC; i += TPB) ob[i] = 0.0f;
    __syncthreads();

    if (tid < KK) {
        u64 k = topk[tid];
        float val = mono2f((u32)(k >> 32));
        u32 idx = ~((u32)k);
        int ci  = (int)(idx >> 12);
        int rem = (int)(idx & 4095u);
        int y   = rem >> 6;
        int xq  = rem & 63;
        float* row = ob + tid * OUTC;
        row[ci]     = 1.0f;
        row[CC + 0] = val;
        row[CC + 1] = (float)xq * (1.0f / (WW - 1));
        row[CC + 2] = (float)y  * (1.0f / (HH - 1));
    }
}

extern "C" void kernel_launch(void* const* d_in, const int* in_sizes, int n_in,
                              void* d_out, int out_size) {
    const float* x = (const float*)d_in[0];
    float* out = (float*)d_out;

    k_thresh<<<BB, TPB>>>(x);
    dim3 gf(CH, BB);
    k_filter<<<gf, TPB>>>(x);
    k_select<<<BB, TPB>>>(x, out);
}

// round 5
// speedup vs baseline: 3.5829x; 1.2639x over previous
#include <cuda_runtime.h>
#include <stdint.h>

// Problem: B=64, C=256, H=64, W=64, k=8.  out: [64, 8, 259] fp32
#define BB   64
#define CC   256
#define HH   64
#define WW   64
#define NPB  (1 << 20)          // elements per batch (C*H*W)
#define KK   8
#define OUTC (CC + 3)           // 259
#define CAP  4096               // candidate capacity per batch

#define CH     16               // filter chunks per batch
#define CHUNK  (NPB / CH)       // 65536 elements
#define TPB    256
#define GROUPS 8                // groups/thread in filter (8*32 = 256 elem/thread)

#define TPB_T  512              // threshold kernel threads

typedef unsigned long long u64;
typedef unsigned int u32;

__device__ u64   g_cand[BB * CAP];
__device__ int   g_count[BB];
__device__ float g_tf[BB];      // float threshold (exact compare in slow path)
__device__ u32   g_tb[BB];      // bit threshold for fast unsigned compare (0 if T<0)

// monotonic float<->uint mapping (total order matches float compare)
__device__ __forceinline__ u32 f2mono(float f) {
    u32 b = __float_as_uint(f);
    return b ^ ((u32)((int)b >> 31) | 0x80000000u);
}
__device__ __forceinline__ float mono2f(u32 m) {
    u32 b = (m & 0x80000000u) ? (m ^ 0x80000000u) : ~m;
    return __uint_as_float(b);
}
__device__ __forceinline__ u64 make_key(float v, u32 idx) {
    return ((u64)f2mono(v) << 32) | (u32)(~idx);
}

// exact top-8 insert by key (value desc, index asc) — matches lax.top_k
__device__ __forceinline__ void consider_key(u64 (&top)[KK], u64 key) {
    if (key > top[KK - 1]) {
        top[KK - 1] = key;
        #pragma unroll
        for (int j = KK - 1; j > 0; --j) {
            if (top[j] > top[j - 1]) { u64 t = top[j]; top[j] = top[j - 1]; top[j - 1] = t; }
        }
    }
}

// ───────────── Pass A: branch-free threshold (min of 8 disjoint group maxes) ─
// Sample = first 65536 elements of the batch, partitioned into 8 disjoint
// groups by (tid & 7). The 8 group maxes are 8 distinct positions, all >= T,
// so T = min(group maxes) <= true 8th-largest: filter never drops a winner.
__global__ __launch_bounds__(TPB_T)
void k_thresh(const float* __restrict__ x) {
    const int b = blockIdx.x;
    const int tid = threadIdx.x;
    if (tid == 0) g_count[b] = 0;

    const float4* __restrict__ p = (const float4*)(x + (size_t)b * NPB);
    const float NEG_INF = -__int_as_float(0x7f800000);

    float m0 = NEG_INF, m1 = NEG_INF, m2 = NEG_INF, m3 = NEG_INF;
    #pragma unroll 8
    for (int i = 0; i < 32; ++i) {              // 32 float4 = 128 elems/thread
        float4 v = p[i * TPB_T + tid];
        m0 = fmaxf(m0, v.x); m1 = fmaxf(m1, v.y);
        m2 = fmaxf(m2, v.z); m3 = fmaxf(m3, v.w);
    }
    float m = fmaxf(fmaxf(m0, m1), fmaxf(m2, m3));

    // group = tid & 7. Within a warp, lanes g, g+8, g+16, g+24 share a group.
    m = fmaxf(m, __shfl_xor_sync(0xFFFFFFFFu, m, 8));
    m = fmaxf(m, __shfl_xor_sync(0xFFFFFFFFu, m, 16));

    __shared__ float gsm[(TPB_T / 32) * 8];
    const int lane = tid & 31, warp = tid >> 5;
    if (lane < 8) gsm[warp * 8 + lane] = m;
    __syncthreads();

    if (tid < 8) {
        float gm = NEG_INF;
        #pragma unroll
        for (int w = 0; w < TPB_T / 32; ++w)
            gm = fmaxf(gm, gsm[w * 8 + tid]);
        // min over the 8 group maxes (threads 0..7)
        float mn = gm;
        #pragma unroll
        for (int off = 4; off > 0; off >>= 1)
            mn = fminf(mn, __shfl_xor_sync(0x000000FFu, mn, off));
        if (tid == 0) {
            g_tf[b] = mn;
            g_tb[b] = (mn >= 0.0f) ? __float_as_uint(mn) : 0u;
        }
    }
}

// ───────────────────────── Pass B: stream + filter + compact ────────────────
__device__ __forceinline__ void emit(int b, float v, u32 idx) {
    int s = atomicAdd(&g_count[b], 1);
    if (s < CAP) g_cand[b * CAP + s] = make_key(v, idx);
}

__global__ __launch_bounds__(TPB)
void k_filter(const float* __restrict__ x) {
    const int c = blockIdx.x;
    const int b = blockIdx.y;
    const int tid = threadIdx.x;
    const u32 TB = g_tb[b];
    const float TF = g_tf[b];
    const u32 cbase = (u32)c * CHUNK;
    const uint4* __restrict__ p = (const uint4*)(x + (size_t)b * NPB + cbase);

    #pragma unroll 4
    for (int i = 0; i < GROUPS; ++i) {
        uint4 q[8];
        #pragma unroll
        for (int j = 0; j < 8; ++j)
            q[j] = p[(i * 8 + j) * TPB + tid];

        // DPX 3-input unsigned max tree: 32 values -> 1 in 16 ops.
        // Unsigned bit compare is exact for non-negative floats; negatives/NaN
        // compare high -> false positives only (rechecked exactly below).
        u32 s0 = __vimax3_u32(q[0].x, q[0].y, q[0].z);
        u32 s1 = __vimax3_u32(q[1].x, q[1].y, q[1].z);
        u32 s2 = __vimax3_u32(q[2].x, q[2].y, q[2].z);
        u32 s3 = __vimax3_u32(q[3].x, q[3].y, q[3].z);
        u32 s4 = __vimax3_u32(q[4].x, q[4].y, q[4].z);
        u32 s5 = __vimax3_u32(q[5].x, q[5].y, q[5].z);
        u32 s6 = __vimax3_u32(q[6].x, q[6].y, q[6].z);
        u32 s7 = __vimax3_u32(q[7].x, q[7].y, q[7].z);
        u32 u0 = __vimax3_u32(s0, s1, q[0].w);
        u32 u1 = __vimax3_u32(s2, s3, q[1].w);
        u32 u2 = __vimax3_u32(s4, s5, q[2].w);
        u32 u3 = __vimax3_u32(s6, s7, q[3].w);
        u32 v0 = __vimax3_u32(u0, u1, q[4].w);
        u32 v1 = __vimax3_u32(u2, u3, q[5].w);
        u32 mm = __vimax3_u32(v0, v1, q[6].w);
        mm     = __vimax3_u32(mm, q[7].w, 0u);

        if (mm >= TB) {
            #pragma unroll
            for (int j = 0; j < 8; ++j) {
                u32 e = cbase + ((u32)(i * 8 + j) * TPB + (u32)tid) * 4u;
                float v0f = __uint_as_float(q[j].x);
                float v1f = __uint_as_float(q[j].y);
                float v2f = __uint_as_float(q[j].z);
                float v3f = __uint_as_float(q[j].w);
                if (v0f >= TF) emit(b, v0f, e + 0u);
                if (v1f >= TF) emit(b, v1f, e + 1u);
                if (v2f >= TF) emit(b, v2f, e + 2u);
                if (v3f >= TF) emit(b, v3f, e + 3u);
            }
        }
    }
}

// ───────────────────────── Pass C: select exact top-8 + emit output ────────
__global__ __launch_bounds__(TPB)
void k_select(const float* __restrict__ x, float* __restrict__ out) {
    const int b = blockIdx.x;
    const int tid = threadIdx.x;
    const int cnt = g_count[b];

    u64 top[KK];
    #pragma unroll
    for (int j = 0; j < KK; ++j) top[j] = 0ull;

    if (cnt >= KK && cnt <= CAP) {
        for (int i = tid; i < cnt; i += TPB)
            consider_key(top, g_cand[b * CAP + i]);
    } else {
        // fallback: exact brute-force scan of the whole batch (cold path)
        const float4* __restrict__ p = (const float4*)(x + (size_t)b * NPB);
        for (int i = tid; i < NPB / 4; i += TPB) {
            float4 v = p[i];
            u32 e = (u32)i * 4u;
            consider_key(top, make_key(v.x, e + 0u));
            consider_key(top, make_key(v.y, e + 1u));
            consider_key(top, make_key(v.z, e + 2u));
            consider_key(top, make_key(v.w, e + 3u));
        }
    }

    __shared__ u64 cand[TPB * KK];
    __shared__ u64 wmax[TPB / 32];
    __shared__ u64 winner;
    __shared__ u64 topk[KK];
    #pragma unroll
    for (int j = 0; j < KK; ++j) cand[tid * KK + j] = top[j];
    __syncthreads();

    const int lane = tid & 31, warp = tid >> 5;
    for (int sel = 0; sel < KK; ++sel) {
        u64 m = 0ull;
        #pragma unroll
        for (int j = 0; j < KK; ++j) { u64 cc = cand[tid * KK + j]; if (cc > m) m = cc; }
        #pragma unroll
        for (int off = 16; off > 0; off >>= 1) {
            u64 o = __shfl_down_sync(0xFFFFFFFFu, m, off);
            if (o > m) m = o;
        }
        if (lane == 0) wmax[warp] = m;
        __syncthreads();
        if (tid == 0) {
            u64 w = 0ull;
            #pragma unroll
            for (int q = 0; q < TPB / 32; ++q) if (wmax[q] > w) w = wmax[q];
            winner = w;
            topk[sel] = w;
        }
        __syncthreads();
        u64 w = winner;
        #pragma unroll
        for (int j = 0; j < KK; ++j)
            if (cand[tid * KK + j] == w) cand[tid * KK + j] = 0ull;
        __syncthreads();
    }

    float* ob = out + (size_t)b * KK * OUTC;
    for (int i = tid; i < KK * OUTC; i += TPB) ob[i] = 0.0f;
    __syncthreads();

    if (tid < KK) {
        u64 k = topk[tid];
        float val = mono2f((u32)(k >> 32));
        u32 idx = ~((u32)k);
        int ci  = (int)(idx >> 12);
        int rem = (int)(idx & 4095u);
        int y   = rem >> 6;
        int xq  = rem & 63;
        float* row = ob + tid * OUTC;
        row[ci]     = 1.0f;
        row[CC + 0] = val;
        row[CC + 1] = (float)xq * (1.0f / (WW - 1));
        row[CC + 2] = (float)y  * (1.0f / (HH - 1));
    }
}

extern "C" void kernel_launch(void* const* d_in, const int* in_sizes, int n_in,
                              void* d_out, int out_size) {
    const float* x = (const float*)d_in[0];
    float* out = (float*)d_out;

    k_thresh<<<BB, TPB_T>>>(x);
    dim3 gf(CH, BB);
    k_filter<<<gf, TPB>>>(x);
    k_select<<<BB, TPB>>>(x, out);
}